// round 16
// baseline (speedup 1.0000x reference)
#include <cuda_runtime.h>
#include <cstdint>
#include <cstddef>

// Problem constants (fixed by the dataset)
#define NNODES 100000
#define MAXE   1600000
#define FIN  128
#define FHID 128
#define FOUT 64

// -------- scratch (allocation-free: __device__ globals) --------
__device__ int   g_is64;                       // 1 if edge_index is int64
__device__ int   g_src[MAXE];                  // converted int32 src
__device__ int   g_dst[MAXE];                  // converted int32 dst
__device__ float g_dinv[NNODES];               // deg -> rsqrt(deg) in place
__device__ float g_h   [(size_t)NNODES*FHID];  // h (x@W1), later relu(agg+b1)
__device__ float g_agg [(size_t)NNODES*FHID];  // layer-1 aggregate
__device__ float g_h64 [(size_t)NNODES*FOUT];  // h2 (h1@W2)
__device__ float g_agg2[(size_t)NNODES*FOUT];  // layer-2 aggregate

// -------- index dtype detection + conversion --------
__global__ void detect_idx_width(const void* ei, int E, int* flag) {
    // int64 node indices are < NNODES; int32 data misread as int64 fuses two
    // indices into lo + hi*2^32 (huge unless hi==0). 8 samples decide it.
    const long long* p = (const long long*)ei;
    int ok = 1;
    int m = E < 8 ? E : 8;
    for (int i = 0; i < m; i++) {
        long long v = p[i];
        if (v < 0 || v >= NNODES) { ok = 0; break; }
    }
    *flag = ok;
}

__global__ void convert_idx(const void* ei, int* src, int* dst, int E,
                            const int* flag) {
    int i = blockIdx.x * blockDim.x + threadIdx.x;
    if (i >= E) return;
    if (*flag) {
        const long long* p = (const long long*)ei;
        src[i] = (int)p[i];
        dst[i] = (int)p[E + i];
    } else {
        const int* p = (const int*)ei;
        src[i] = p[i];
        dst[i] = p[E + i];
    }
}

// -------- small elementwise kernels --------
__global__ void init_deg(float* deg, int n) {
    int i = blockIdx.x * blockDim.x + threadIdx.x;
    if (i < n) deg[i] = 1.0f;   // +1 self loop
}

__global__ void count_deg(const int* __restrict__ dst, float* deg, int E) {
    int e = blockIdx.x * blockDim.x + threadIdx.x;
    if (e < E) atomicAdd(&deg[dst[e]], 1.0f);
}

__global__ void finalize_dinv(float* deg, int n) {
    int i = blockIdx.x * blockDim.x + threadIdx.x;
    if (i < n) deg[i] = rsqrtf(deg[i]);
}

__global__ void relu_bias(const float* __restrict__ agg, const float* __restrict__ b,
                          float* __restrict__ out, int total) {
    int i = blockIdx.x * blockDim.x + threadIdx.x;
    if (i < total) out[i] = fmaxf(agg[i] + b[i & (FHID - 1)], 0.0f);
}

__global__ void add_bias(const float* __restrict__ agg, const float* __restrict__ b,
                         float* __restrict__ out, int total) {
    int i = blockIdx.x * blockDim.x + threadIdx.x;
    if (i < total) out[i] = agg[i] + b[i & (FOUT - 1)];
}

// -------- GEMM: C[n,BN] = A[n,K] @ W[K,BN], fused epilogues --------
// MODE 0: Ch = A@W ; Cagg = (A@W) * dinv[row]^2      (GCN pre-aggregation)
// MODE 1: Ch = A@W + bias                            (decoder)
template<int BN, int TN, int MODE>
__global__ void __launch_bounds__(256)
gemm_kernel(const float* __restrict__ A, const float* __restrict__ W,
            const float* __restrict__ bias, const float* __restrict__ dinv,
            float* __restrict__ Ch, float* __restrict__ Cagg,
            int n, int K) {
    constexpr int BM = 64, BK = 16, TM = 4;
    constexpr int APAD = 4;                  // keep 16B alignment of As rows
    __shared__ float As[BK][BM + APAD];
    __shared__ float Ws[BK][BN];

    const int tid = threadIdx.x;
    const int tr  = tid / (BN / TN);         // 0..15
    const int tc  = tid % (BN / TN);         // 0..15
    const int row0 = blockIdx.x * BM;

    float acc[TM][TN];
#pragma unroll
    for (int m = 0; m < TM; m++)
#pragma unroll
        for (int t = 0; t < TN; t++) acc[m][t] = 0.0f;

    for (int k0 = 0; k0 < K; k0 += BK) {
#pragma unroll
        for (int i = tid; i < BM * BK; i += 256) {
            int r = i / BK, k = i % BK;
            int row = row0 + r;
            As[k][r] = (row < n) ? A[(size_t)row * K + k0 + k] : 0.0f;
        }
#pragma unroll
        for (int i = tid; i < BK * BN; i += 256) {
            int k = i / BN, c = i % BN;
            Ws[k][c] = W[(size_t)(k0 + k) * BN + c];
        }
        __syncthreads();

#pragma unroll
        for (int kk = 0; kk < BK; kk++) {
            float ar[TM], wr[TN];
            *(float4*)&ar[0] = *(const float4*)&As[kk][tr * TM];
            *(float4*)&wr[0] = *(const float4*)&Ws[kk][tc * TN];
            if (TN == 8)
                *(float4*)&wr[4] = *(const float4*)&Ws[kk][tc * TN + 4];
#pragma unroll
            for (int m = 0; m < TM; m++)
#pragma unroll
                for (int t = 0; t < TN; t++)
                    acc[m][t] += ar[m] * wr[t];
        }
        __syncthreads();
    }

#pragma unroll
    for (int m = 0; m < TM; m++) {
        int row = row0 + tr * TM + m;
        if (row >= n) continue;
        float dsc = (MODE == 0) ? dinv[row] * dinv[row] : 0.0f;
#pragma unroll
        for (int t = 0; t < TN; t++) {
            int col = tc * TN + t;
            float v = acc[m][t];
            if (MODE == 0) {
                Ch  [(size_t)row * BN + col] = v;
                Cagg[(size_t)row * BN + col] = v * dsc;
            } else {
                Ch[(size_t)row * BN + col] = v + bias[col];
            }
        }
    }
}

// -------- edge scatter: warp per edge, SCALAR atomicAdd (vector f32 RED
// traps on sm_103a — verified R1/R2). Lane-strided features keep each RED
// wavefront a coalesced 128B burst. --------
// VEC = features per lane (4 -> F=128, 2 -> F=64)
template<int VEC>
__global__ void __launch_bounds__(256)
edge_aggregate(const int* __restrict__ src,
               const int* __restrict__ dst,
               const float* __restrict__ dinv,
               const float* __restrict__ h,
               float* __restrict__ agg, int E) {
    int warp = (blockIdx.x * blockDim.x + threadIdx.x) >> 5;
    int lane = threadIdx.x & 31;
    if (warp >= E) return;
    int s = src[warp];
    int d = dst[warp];
    float coef = dinv[s] * dinv[d];
    constexpr int F = 32 * VEC;
    const float* hp = h + (size_t)s * F;
    float* ap = agg + (size_t)d * F;
#pragma unroll
    for (int j = 0; j < VEC; j++) {
        int f = lane + j * 32;
        atomicAdd(ap + f, __ldg(hp + f) * coef);
    }
}

// -------- host launcher --------
extern "C" void kernel_launch(void* const* d_in, const int* in_sizes, int n_in,
                              void* d_out, int out_size) {
    const float* x  = (const float*)d_in[0];
    const void*  ei = d_in[1];
    const float* W1 = (const float*)d_in[2];
    const float* b1 = (const float*)d_in[3];
    const float* W2 = (const float*)d_in[4];
    const float* b2 = (const float*)d_in[5];
    const float* Wd = (const float*)d_in[6];
    const float* bd = (const float*)d_in[7];

    const int n = in_sizes[0] / FIN;        // 100000
    const int E = in_sizes[1] / 2;          // 1600000

    float* xrec = (float*)d_out;                       // [n,128]
    float* z    = (float*)d_out + (size_t)n * FIN;     // [n,64]

    int *is64, *src, *dst;
    float *dinv, *h, *agg, *h64, *agg2;
    cudaGetSymbolAddress((void**)&is64, g_is64);
    cudaGetSymbolAddress((void**)&src,  g_src);
    cudaGetSymbolAddress((void**)&dst,  g_dst);
    cudaGetSymbolAddress((void**)&dinv, g_dinv);
    cudaGetSymbolAddress((void**)&h,    g_h);
    cudaGetSymbolAddress((void**)&agg,  g_agg);
    cudaGetSymbolAddress((void**)&h64,  g_h64);
    cudaGetSymbolAddress((void**)&agg2, g_agg2);

    const int T = 256;

    // 0) normalize edge indices to int32 (harness may deliver int32 or int64)
    detect_idx_width<<<1, 1>>>(ei, E, is64);
    convert_idx<<<(E + T - 1) / T, T>>>(ei, src, dst, E, is64);

    // 1) degrees -> dinv
    init_deg<<<(n + T - 1) / T, T>>>(dinv, n);
    count_deg<<<(E + T - 1) / T, T>>>(dst, dinv, E);
    finalize_dinv<<<(n + T - 1) / T, T>>>(dinv, n);

    const int gblocks = (n + 63) / 64;
    const long long ewarps = (long long)E * 32;
    const int eblocks = (int)((ewarps + T - 1) / T);

    // 2) layer 1: h = x@W1, agg = h*dinv^2 ; scatter ; h1 = relu(agg+b1)
    gemm_kernel<FHID, 8, 0><<<gblocks, T>>>(x, W1, nullptr, dinv, h, agg, n, FIN);
    edge_aggregate<4><<<eblocks, T>>>(src, dst, dinv, h, agg, E);
    relu_bias<<<((size_t)n * FHID + T - 1) / T, T>>>(agg, b1, h, n * FHID);

    // 3) layer 2: h2 = h1@W2, agg2 = h2*dinv^2 ; scatter ; z = agg2+b2
    gemm_kernel<FOUT, 4, 0><<<gblocks, T>>>(h, W2, nullptr, dinv, h64, agg2, n, FHID);
    edge_aggregate<2><<<eblocks, T>>>(src, dst, dinv, h64, agg2, E);
    add_bias<<<((size_t)n * FOUT + T - 1) / T, T>>>(agg2, b2, z, n * FOUT);

    // 4) decoder: x_recon = z@Wd + bd
    gemm_kernel<FIN, 8, 1><<<gblocks, T>>>(z, Wd, bd, nullptr, xrec, nullptr, n, FOUT);
}

// round 17
// speedup vs baseline: 1.7130x; 1.7130x over previous
#include <cuda_runtime.h>
#include <cstdint>
#include <cstddef>

// Problem constants (fixed by the dataset)
#define NNODES 100000
#define MAXE   1600000
#define FIN  128
#define FHID 128
#define FOUT 64

#define SCAN_B 1024
#define NSCANBLK ((NNODES + SCAN_B - 1) / SCAN_B)   // 98

// -------- scratch (allocation-free: __device__ globals) --------
__device__ int   g_is64;                        // 1 if edge_index is int64
__device__ int   g_src[MAXE];                   // converted int32 src
__device__ int   g_dst[MAXE];                   // converted int32 dst
__device__ int   g_cnt[NNODES];                 // in-degree counts
__device__ int   g_rowptr[NNODES + 1];          // CSR row pointers (by dst)
__device__ int   g_cursor[NNODES];              // fill cursors
__device__ int   g_bsums[NSCANBLK + 1];         // scan partials
__device__ int   g_csrc[MAXE];                  // CSR column (src) indices
__device__ float g_dinv[NNODES];                // rsqrt(deg)
__device__ float g_h   [(size_t)NNODES*FHID];   // h  = x@W1
__device__ float g_h1  [(size_t)NNODES*FHID];   // h1 = relu(agg1 + b1)
__device__ float g_h64 [(size_t)NNODES*FOUT];   // h2 = h1@W2

// -------- index dtype detection + conversion --------
__global__ void detect_idx_width(const void* ei, int E, int* flag) {
    const long long* p = (const long long*)ei;
    int ok = 1;
    int m = E < 8 ? E : 8;
    for (int i = 0; i < m; i++) {
        long long v = p[i];
        if (v < 0 || v >= NNODES) { ok = 0; break; }
    }
    *flag = ok;
}

__global__ void convert_idx(const void* ei, int* src, int* dst, int E,
                            const int* flag) {
    int i = blockIdx.x * blockDim.x + threadIdx.x;
    if (i >= E) return;
    if (*flag) {
        const long long* p = (const long long*)ei;
        src[i] = (int)p[i];
        dst[i] = (int)p[E + i];
    } else {
        const int* p = (const int*)ei;
        src[i] = p[i];
        dst[i] = p[E + i];
    }
}

// -------- degree count + dinv --------
__global__ void zero_cnt(int* cnt, int n) {
    int i = blockIdx.x * blockDim.x + threadIdx.x;
    if (i < n) cnt[i] = 0;
}

__global__ void count_indeg(const int* __restrict__ dst, int* cnt, int E) {
    int e = blockIdx.x * blockDim.x + threadIdx.x;
    if (e < E) atomicAdd(&cnt[dst[e]], 1);
}

__global__ void make_dinv(const int* __restrict__ cnt, float* dinv, int n) {
    int i = blockIdx.x * blockDim.x + threadIdx.x;
    if (i < n) dinv[i] = rsqrtf((float)cnt[i] + 1.0f);   // +1 self loop
}

// -------- exclusive scan (two level) --------
__global__ void scan_block(const int* __restrict__ cnt, int* out,
                           int* bsums, int n) {
    __shared__ int temp[SCAN_B];
    int gid = blockIdx.x * SCAN_B + threadIdx.x;
    int v = (gid < n) ? cnt[gid] : 0;
    temp[threadIdx.x] = v;
    __syncthreads();
#pragma unroll
    for (int off = 1; off < SCAN_B; off <<= 1) {
        int t = (threadIdx.x >= off) ? temp[threadIdx.x - off] : 0;
        __syncthreads();
        temp[threadIdx.x] += t;
        __syncthreads();
    }
    if (gid <= n && gid < (blockIdx.x + 1) * SCAN_B)  // within block range
        if (gid < n) out[gid] = temp[threadIdx.x] - v;  // exclusive
    if (threadIdx.x == SCAN_B - 1) bsums[blockIdx.x] = temp[SCAN_B - 1];
}

__global__ void scan_sums(int* bsums, int nb) {
    int acc = 0;
    for (int i = 0; i < nb; i++) { int t = bsums[i]; bsums[i] = acc; acc += t; }
}

__global__ void scan_add(int* rowptr, int* cursor, const int* __restrict__ bsums,
                         int n, int E) {
    int gid = blockIdx.x * SCAN_B + threadIdx.x;
    if (gid < n) {
        int v = rowptr[gid] + bsums[blockIdx.x];
        rowptr[gid] = v;
        cursor[gid] = v;
    }
    if (gid == 0) rowptr[n] = E;
}

// -------- CSR fill --------
__global__ void fill_csr(const int* __restrict__ src, const int* __restrict__ dst,
                         int* cursor, int* csrc, int E) {
    int e = blockIdx.x * blockDim.x + threadIdx.x;
    if (e >= E) return;
    int pos = atomicAdd(&cursor[dst[e]], 1);
    csrc[pos] = src[e];
}

// -------- GEMM: C[n,BN] = A[n,K] @ W[K,BN] (+bias if BIAS) --------
template<int BN, int TN, bool BIAS>
__global__ void __launch_bounds__(256)
gemm_kernel(const float* __restrict__ A, const float* __restrict__ W,
            const float* __restrict__ bias,
            float* __restrict__ C, int n, int K) {
    constexpr int BM = 64, BK = 16, TM = 4;
    constexpr int APAD = 4;
    __shared__ float As[BK][BM + APAD];
    __shared__ float Ws[BK][BN];

    const int tid = threadIdx.x;
    const int tr  = tid / (BN / TN);
    const int tc  = tid % (BN / TN);
    const int row0 = blockIdx.x * BM;

    float acc[TM][TN];
#pragma unroll
    for (int m = 0; m < TM; m++)
#pragma unroll
        for (int t = 0; t < TN; t++) acc[m][t] = 0.0f;

    for (int k0 = 0; k0 < K; k0 += BK) {
#pragma unroll
        for (int i = tid; i < BM * BK; i += 256) {
            int r = i / BK, k = i % BK;
            int row = row0 + r;
            As[k][r] = (row < n) ? A[(size_t)row * K + k0 + k] : 0.0f;
        }
#pragma unroll
        for (int i = tid; i < BK * BN; i += 256) {
            int k = i / BN, c = i % BN;
            Ws[k][c] = W[(size_t)(k0 + k) * BN + c];
        }
        __syncthreads();

#pragma unroll
        for (int kk = 0; kk < BK; kk++) {
            float ar[TM], wr[TN];
            *(float4*)&ar[0] = *(const float4*)&As[kk][tr * TM];
            *(float4*)&wr[0] = *(const float4*)&Ws[kk][tc * TN];
            if (TN == 8)
                *(float4*)&wr[4] = *(const float4*)&Ws[kk][tc * TN + 4];
#pragma unroll
            for (int m = 0; m < TM; m++)
#pragma unroll
                for (int t = 0; t < TN; t++)
                    acc[m][t] += ar[m] * wr[t];
        }
        __syncthreads();
    }

#pragma unroll
    for (int m = 0; m < TM; m++) {
        int row = row0 + tr * TM + m;
        if (row >= n) continue;
#pragma unroll
        for (int t = 0; t < TN; t++) {
            int col = tc * TN + t;
            float v = acc[m][t];
            if (BIAS) v += bias[col];
            C[(size_t)row * BN + col] = v;
        }
    }
}

// -------- CSR gather: warp per dst node, register accumulation --------
// F = feature width (128 -> float4/lane, 64 -> float2/lane)
// Fuses self-loop, bias add, and optional relu. No atomics.
template<int F, bool RELU>
__global__ void __launch_bounds__(256)
gather_csr(const int* __restrict__ rowptr, const int* __restrict__ csrc,
           const float* __restrict__ dinv, const float* __restrict__ h,
           const float* __restrict__ bias, float* __restrict__ out, int n) {
    int node = (blockIdx.x * blockDim.x + threadIdx.x) >> 5;
    int lane = threadIdx.x & 31;
    if (node >= n) return;

    int beg = rowptr[node];
    int end = rowptr[node + 1];
    float di = dinv[node];

    if (F == 128) {
        const float4* hrow = (const float4*)(h + (size_t)node * 128);
        float4 acc = hrow[lane];
        float dsc = di * di;
        acc.x *= dsc; acc.y *= dsc; acc.z *= dsc; acc.w *= dsc;
        for (int e = beg; e < end; e += 32) {
            int batch = min(32, end - e);
            int s_l = 0; float c_l = 0.0f;
            if (lane < batch) { s_l = csrc[e + lane]; c_l = dinv[s_l]; }
            for (int j = 0; j < batch; j++) {
                int   s = __shfl_sync(0xffffffffu, s_l, j);
                float c = __shfl_sync(0xffffffffu, c_l, j) * di;
                float4 v = *((const float4*)(h + (size_t)s * 128) + lane);
                acc.x += v.x * c; acc.y += v.y * c;
                acc.z += v.z * c; acc.w += v.w * c;
            }
        }
        float4 bb = ((const float4*)bias)[lane];
        acc.x += bb.x; acc.y += bb.y; acc.z += bb.z; acc.w += bb.w;
        if (RELU) {
            acc.x = fmaxf(acc.x, 0.0f); acc.y = fmaxf(acc.y, 0.0f);
            acc.z = fmaxf(acc.z, 0.0f); acc.w = fmaxf(acc.w, 0.0f);
        }
        ((float4*)(out + (size_t)node * 128))[lane] = acc;
    } else {
        const float2* hrow = (const float2*)(h + (size_t)node * 64);
        float2 acc = hrow[lane];
        float dsc = di * di;
        acc.x *= dsc; acc.y *= dsc;
        for (int e = beg; e < end; e += 32) {
            int batch = min(32, end - e);
            int s_l = 0; float c_l = 0.0f;
            if (lane < batch) { s_l = csrc[e + lane]; c_l = dinv[s_l]; }
            for (int j = 0; j < batch; j++) {
                int   s = __shfl_sync(0xffffffffu, s_l, j);
                float c = __shfl_sync(0xffffffffu, c_l, j) * di;
                float2 v = *((const float2*)(h + (size_t)s * 64) + lane);
                acc.x += v.x * c; acc.y += v.y * c;
            }
        }
        float2 bb = ((const float2*)bias)[lane];
        acc.x += bb.x; acc.y += bb.y;
        if (RELU) { acc.x = fmaxf(acc.x, 0.0f); acc.y = fmaxf(acc.y, 0.0f); }
        ((float2*)(out + (size_t)node * 64))[lane] = acc;
    }
}

// -------- host launcher --------
extern "C" void kernel_launch(void* const* d_in, const int* in_sizes, int n_in,
                              void* d_out, int out_size) {
    const float* x  = (const float*)d_in[0];
    const void*  ei = d_in[1];
    const float* W1 = (const float*)d_in[2];
    const float* b1 = (const float*)d_in[3];
    const float* W2 = (const float*)d_in[4];
    const float* b2 = (const float*)d_in[5];
    const float* Wd = (const float*)d_in[6];
    const float* bd = (const float*)d_in[7];

    const int n = in_sizes[0] / FIN;        // 100000
    const int E = in_sizes[1] / 2;          // 1600000

    float* xrec = (float*)d_out;                       // [n,128]
    float* z    = (float*)d_out + (size_t)n * FIN;     // [n,64]

    int *is64, *src, *dst, *cnt, *rowptr, *cursor, *bsums, *csrc;
    float *dinv, *h, *h1, *h64;
    cudaGetSymbolAddress((void**)&is64,   g_is64);
    cudaGetSymbolAddress((void**)&src,    g_src);
    cudaGetSymbolAddress((void**)&dst,    g_dst);
    cudaGetSymbolAddress((void**)&cnt,    g_cnt);
    cudaGetSymbolAddress((void**)&rowptr, g_rowptr);
    cudaGetSymbolAddress((void**)&cursor, g_cursor);
    cudaGetSymbolAddress((void**)&bsums,  g_bsums);
    cudaGetSymbolAddress((void**)&csrc,   g_csrc);
    cudaGetSymbolAddress((void**)&dinv,   g_dinv);
    cudaGetSymbolAddress((void**)&h,      g_h);
    cudaGetSymbolAddress((void**)&h1,     g_h1);
    cudaGetSymbolAddress((void**)&h64,    g_h64);

    const int T = 256;
    const int nblk = (n + T - 1) / T;
    const int eblk = (E + T - 1) / T;
    const int sblk = (n + SCAN_B - 1) / SCAN_B;

    // 0) normalize edge indices to int32
    detect_idx_width<<<1, 1>>>(ei, E, is64);
    convert_idx<<<eblk, T>>>(ei, src, dst, E, is64);

    // 1) CSR build (by dst) + dinv
    zero_cnt<<<nblk, T>>>(cnt, n);
    count_indeg<<<eblk, T>>>(dst, cnt, E);
    make_dinv<<<nblk, T>>>(cnt, dinv, n);
    scan_block<<<sblk, SCAN_B>>>(cnt, rowptr, bsums, n);
    scan_sums<<<1, 1>>>(bsums, sblk);
    scan_add<<<sblk, SCAN_B>>>(rowptr, cursor, bsums, n, E);
    fill_csr<<<eblk, T>>>(src, dst, cursor, csrc, E);

    const int gblocks = (n + 63) / 64;
    const int wblocks = (int)(((long long)n * 32 + T - 1) / T);

    // 2) layer 1: h = x@W1 ; h1 = relu(gather(h) + b1)
    gemm_kernel<FHID, 8, false><<<gblocks, T>>>(x, W1, nullptr, h, n, FIN);
    gather_csr<128, true><<<wblocks, T>>>(rowptr, csrc, dinv, h, b1, h1, n);

    // 3) layer 2: h64 = h1@W2 ; z = gather(h64) + b2
    gemm_kernel<FOUT, 4, false><<<gblocks, T>>>(h1, W2, nullptr, h64, n, FHID);
    gather_csr<64, false><<<wblocks, T>>>(rowptr, csrc, dinv, h64, b2, z, n);

    // 4) decoder: x_recon = z@Wd + bd
    gemm_kernel<FIN, 8, true><<<gblocks, T>>>(z, Wd, bd, xrec, n, FOUT);
}